// round 15
// baseline (speedup 1.0000x reference)
#include <cuda_runtime.h>
#include <cuda_bf16.h>
#include <cstdint>
#include <cstddef>

typedef unsigned long long u64;
typedef unsigned int u32;

#define BATCH 8
#define SEQ   512
#define DIM   1024
#define NVOC  32064
#define NVOC_PAD 32128          // 251 * 128
#define NCTA  128
#define JT    8
#define RNN_THREADS 256

// padded act layout: 8 chunks of 128 floats, each chunk padded to 528 B
#define CHUNK_B 528
#define ROW_B   (8 * CHUNK_B)               // 4224 B per batch row
#define ACT_F   (BATCH * ROW_B / 4)         // 8448 floats per act buffer
#define RNN_SMEM ((3 * ACT_F + RNN_THREADS * 8) * 4)   // 3 acts + sred

// ---------------- scratch (device globals; no allocation allowed) ----------------
__device__ __align__(16) float g_h0[2][BATCH][DIM];
__device__ __align__(16) float g_h1[2][BATCH][DIM];
__device__ __align__(16) __nv_bfloat16 g_Ahi[BATCH * SEQ * DIM];  // 8 MB
__device__ __align__(16) __nv_bfloat16 g_Alo[BATCH * SEQ * DIM];  // 8 MB
__device__ __align__(16) __nv_bfloat16 g_WhiT[(size_t)NVOC_PAD * DIM]; // 66 MB, pad rows stay 0
__device__ __align__(16) __nv_bfloat16 g_WloT[(size_t)NVOC_PAD * DIM]; // 66 MB
__device__ unsigned g_flags[NCTA];   // per-CTA monotonic arrival counters
__device__ unsigned g_epoch;         // monotonic release counter

// ---------------- packed f32x2 helpers ----------------
__device__ __forceinline__ void fmaX2(u64 &d, u64 a, u64 b) {
    asm("fma.rn.f32x2 %0, %1, %2, %0;" : "+l"(d) : "l"(a), "l"(b));
}
__device__ __forceinline__ u64 pack2(float lo, float hi) {
    u64 d; asm("mov.b64 %0, {%1, %2};" : "=l"(d) : "f"(lo), "f"(hi)); return d;
}
__device__ __forceinline__ float lo32(u64 v) { return __uint_as_float((unsigned)v); }
__device__ __forceinline__ float hi32(u64 v) { return __uint_as_float((unsigned)(v >> 32)); }
__device__ __forceinline__ float sum2(u64 v) { return lo32(v) + hi32(v); }

__device__ __forceinline__ u32 smem_u32(const void* p) {
    u32 a;
    asm("{ .reg .u64 t; cvta.to.shared.u64 t, %1; cvt.u32.u64 %0, t; }" : "=r"(a) : "l"(p));
    return a;
}

// ---------------- HMMA helpers (valid PTX at base sm_103) ----------------
__device__ __forceinline__ void ldsm4(u32* r, u32 addr) {
    asm volatile("ldmatrix.sync.aligned.m8n8.x4.shared.b16 {%0,%1,%2,%3}, [%4];"
        : "=r"(r[0]), "=r"(r[1]), "=r"(r[2]), "=r"(r[3]) : "r"(addr));
}
__device__ __forceinline__ void mma16816(float* c, const u32* a, const u32* b) {
    asm volatile(
        "mma.sync.aligned.m16n8k16.row.col.f32.bf16.bf16.f32 "
        "{%0,%1,%2,%3}, {%4,%5,%6,%7}, {%8,%9}, {%0,%1,%2,%3};"
        : "+f"(c[0]), "+f"(c[1]), "+f"(c[2]), "+f"(c[3])
        : "r"(a[0]), "r"(a[1]), "r"(a[2]), "r"(a[3]), "r"(b[0]), "r"(b[1]));
}
#define CP_ASYNC16(smem, gmem) \
    asm volatile("cp.async.cg.shared.global [%0], [%1], 16;" :: "r"(smem), "l"(gmem))
#define CP_COMMIT() asm volatile("cp.async.commit_group;" ::: "memory")
#define CP_WAIT(n)  asm volatile("cp.async.wait_group %0;" :: "n"(n) : "memory")

// ---- contention-free grid barrier ----
// Each CTA releases its own flag; CTA0's 128 threads poll all flags in
// parallel, then CTA0 releases a single epoch word everyone polls.
// Targets are base+count (base read at launch start) -> monotonic across
// graph replays (every CTA executes the same barrier count per launch).
__device__ __forceinline__ void grid_barrier2(int bid, unsigned target) {
    __syncthreads();
    const int tid = threadIdx.x;
    if (bid == 0) {
        if (tid == 0)
            asm volatile("st.release.gpu.global.u32 [%0], %1;"
                         :: "l"(&g_flags[0]), "r"(target) : "memory");
        if (tid < NCTA) {
            unsigned v;
            do {
                asm volatile("ld.acquire.gpu.global.u32 %0, [%1];"
                             : "=r"(v) : "l"(&g_flags[tid]) : "memory");
            } while (v < target);
        }
        __syncthreads();
        if (tid == 0)
            asm volatile("st.release.gpu.global.u32 [%0], %1;"
                         :: "l"(&g_epoch), "r"(target) : "memory");
    } else {
        if (tid == 0) {
            asm volatile("st.release.gpu.global.u32 [%0], %1;"
                         :: "l"(&g_flags[bid]), "r"(target) : "memory");
            unsigned v;
            do {
                asm volatile("ld.acquire.gpu.global.u32 %0, [%1];"
                             : "=r"(v) : "l"(&g_epoch) : "memory");
            } while (v < target);
        }
    }
    __syncthreads();
}

// =====================================================================
// Persistent RNN, register-resident weights (layer-skew, 1 barrier/step).
// thread -> pl = tid>>6 (0:x.W0 1:h.U0 2:h0.W1 3:h1.U1),
// kc = (tid>>3)&7 (128-float K-chunk), jj = tid&7 (output column).
// Layer-1 epilogue writes bf16 hi/lo directly (fused A-conversion).
// =====================================================================
__global__ void __launch_bounds__(RNN_THREADS, 1)
rnn_kernel(const int* __restrict__ tokens, const float* __restrict__ emb,
           const float* __restrict__ Wh, const float* __restrict__ Uh,
           const float* __restrict__ bias)
{
    extern __shared__ __align__(16) float smem[];
    float* sX   = smem;
    float* sH0  = smem + ACT_F;
    float* sH1  = smem + 2 * ACT_F;
    float* sred = smem + 3 * ACT_F;          // [256][8]

    const int tid = threadIdx.x;
    const int bid = blockIdx.x;
    const int j0  = bid * JT;
    const int jj  = tid & 7;
    const int kc  = (tid >> 3) & 7;
    const int pl  = tid >> 6;

    // barrier bookkeeping: base is this CTA's flag value at launch start
    unsigned bar_base;
    asm volatile("ld.global.cg.u32 %0, [%1];" : "=r"(bar_base) : "l"(&g_flags[bid]));
    unsigned bar_cnt = 0;

    // ---- load this thread's 128-float weight chunk into 64 u64 regs ----
    const float* M = Wh;
    if      (pl == 1) M = Uh;
    else if (pl == 2) M = Wh + DIM * DIM;
    else if (pl == 3) M = Uh + DIM * DIM;
    const int col = j0 + jj;
    const int kbase = kc * 128;
    u64 w[64];
    #pragma unroll
    for (int t = 0; t < 64; t++) {
        float w0 = __ldg(M + (size_t)(kbase + 2 * t) * DIM + col);
        float w1 = __ldg(M + (size_t)(kbase + 2 * t + 1) * DIM + col);
        w[t] = pack2(w0, w1);
    }

    // re-zero hidden states (replay-dirty)
    if (tid < 64) {
        int zb = tid >> 3, zj = j0 + (tid & 7);
        g_h0[0][zb][zj] = 0.f; g_h0[1][zb][zj] = 0.f;
        g_h1[0][zb][zj] = 0.f; g_h1[1][zb][zj] = 0.f;
    }

    // output-thread params (tid < 128): o -> (olyr, ojj, ob)
    const int olyr = (tid >> 6) & 1;
    const int ojj  = (tid >> 3) & 7;
    const int ob   = tid & 7;
    const float bo = (tid < 128) ? bias[olyr * DIM + j0 + ojj] : 0.f;

    // act base for compute (padded layout)
    const char* actb = (const char*)((pl == 0) ? sX : (pl == 3) ? sH1 : sH0);
    actb += kc * CHUNK_B;

    // ---- prefetch X[0] into padded sX ----
    {
        for (int j = 0; j < 8; j++) {
            int v = tid + j * 256;
            int bb = v >> 8, w32 = v & 255;
            int tk = __ldg(tokens + bb * SEQ + 0);
            float4 x = make_float4(0.f, 0.f, 0.f, 0.f);
            if (tk != 0) x = __ldg((const float4*)(emb + (size_t)tk * DIM + w32 * 4));
            *(float4*)((char*)sX + bb * ROW_B + (w32 >> 5) * CHUNK_B + (w32 & 31) * 16) = x;
        }
    }
    bar_cnt++; grid_barrier2(bid, bar_base + bar_cnt);

    for (int s = 0; s <= SEQ; s++) {
        const int pr = (s + 1) & 1;

        // ---- stage h0[s-1], h1[s-2]: batched ldcg -> padded STS ----
        {
            const float4* h0s = (const float4*)&g_h0[pr][0][0];
            const float4* h1s = (const float4*)&g_h1[pr][0][0];
            float4 r0[8], r1[8];
            #pragma unroll
            for (int j = 0; j < 8; j++) {
                r0[j] = __ldcg(h0s + tid + j * 256);
                r1[j] = __ldcg(h1s + tid + j * 256);
            }
            #pragma unroll
            for (int j = 0; j < 8; j++) {
                int v = tid + j * 256;
                int bb = v >> 8, w32 = v & 255;
                size_t off = bb * ROW_B + (w32 >> 5) * CHUNK_B + (w32 & 31) * 16;
                *(float4*)((char*)sH0 + off) = r0[j];
                *(float4*)((char*)sH1 + off) = r1[j];
            }
        }
        __syncthreads();

        // ---- compute: 8 batches x 128-K chunk, weights in regs ----
        {
            u64 acc[8];
            #pragma unroll
            for (int b = 0; b < 8; b++) acc[b] = 0ull;
            #pragma unroll
            for (int t = 0; t < 32; t++) {
                #pragma unroll
                for (int b = 0; b < 8; b++) {
                    ulonglong2 v = *(const ulonglong2*)(actb + b * ROW_B + t * 16);
                    fmaX2(acc[b], v.x, w[2 * t]);
                    fmaX2(acc[b], v.y, w[2 * t + 1]);
                }
            }
            float* sr = sred + tid * 8;
            #pragma unroll
            for (int b = 0; b < 8; b++) sr[b] = sum2(acc[b]);
        }
        __syncthreads();

        // ---- reduce 16 partials (2 pl x 8 kc) per output, tanh, store ----
        if (tid < 128) {
            const float* base = sred + (olyr * 2) * 512 + ojj * 8 + ob;
            float v = bo;
            #pragma unroll
            for (int q = 0; q < 16; q++) v += base[q * 64];
            float hv = tanhf(v);
            if (olyr == 0) {
                if (s < SEQ) g_h0[s & 1][ob][j0 + ojj] = hv;
            } else if (s >= 1) {
                g_h1[s & 1][ob][j0 + ojj] = hv;
                // fused A-conversion: write bf16 hi/lo directly
                size_t oidx = (size_t)(ob * SEQ + (s - 1)) * DIM + j0 + ojj;
                __nv_bfloat16 hb = __float2bfloat16(hv);
                __nv_bfloat16 lb = __float2bfloat16(hv - __bfloat162float(hb));
                g_Ahi[oidx] = hb;
                g_Alo[oidx] = lb;
            }
        }

        // ---- prefetch X[s+1] BEFORE the barrier ----
        if (s + 1 < SEQ) {
            for (int j = 0; j < 8; j++) {
                int v = tid + j * 256;
                int bb = v >> 8, w32 = v & 255;
                int tk = __ldg(tokens + bb * SEQ + (s + 1));
                float4 x = make_float4(0.f, 0.f, 0.f, 0.f);
                if (tk != 0) x = __ldg((const float4*)(emb + (size_t)tk * DIM + w32 * 4));
                *(float4*)((char*)sX + bb * ROW_B + (w32 >> 5) * CHUNK_B + (w32 & 31) * 16) = x;
            }
        }
        bar_cnt++; grid_barrier2(bid, bar_base + bar_cnt);
    }
}

// =====================================================================
// Convert + transpose W: fc_w[k][n] fp32 -> g_WhiT/g_WloT[n][k] bf16
// =====================================================================
__global__ void __launch_bounds__(256)
convW_kernel(const float* __restrict__ W)
{
    __shared__ float s[32][36];
    const int n0 = blockIdx.x * 32;
    const int k0 = blockIdx.y * 32;
    const int tid = threadIdx.x;
    const int ty = tid >> 3;
    const int tx = (tid & 7) << 2;

    float4 v = *(const float4*)(W + (size_t)(k0 + ty) * NVOC + n0 + tx);
    s[ty][tx + 0] = v.x; s[ty][tx + 1] = v.y;
    s[ty][tx + 2] = v.z; s[ty][tx + 3] = v.w;
    __syncthreads();

    const int r  = tid >> 3;
    const int c4 = (tid & 7) << 2;
    __nv_bfloat16 hi[4], lo[4];
    #pragma unroll
    for (int j = 0; j < 4; j++) {
        float x = s[c4 + j][r];
        hi[j] = __float2bfloat16(x);
        lo[j] = __float2bfloat16(x - __bfloat162float(hi[j]));
    }
    size_t off = (size_t)(n0 + r) * DIM + k0 + c4;
    *(uint2*)(g_WhiT + off) = *(uint2*)hi;
    *(uint2*)(g_WloT + off) = *(uint2*)lo;
}

// =====================================================================
// HMMA projection: C[4096,32064] = A @ W^T + bias, split-bf16 (3 products).
// CTA 128x128xK32, 8 warps (2x4), warp tile 64x32 = 4x4 m16n8k16 frags.
// cp.async double-buffered smem; 80B row stride. Grid M-fastest.
// =====================================================================
#define GSTRIDE 80
#define GTILE   (128 * GSTRIDE)
#define OFF_AHI 0
#define OFF_ALO (1 * GTILE)
#define OFF_BHI (2 * GTILE)
#define OFF_BLO (3 * GTILE)
#define STAGE_BYTES (4 * GTILE)
#define GEMM_SMEM (2 * STAGE_BYTES)
#define NKT (DIM / 32)

__global__ void __launch_bounds__(256, 1)
gemm_hmma_kernel(const float* __restrict__ bias, float* __restrict__ C)
{
    extern __shared__ __align__(16) char smc[];
    const u32 sb = smem_u32(smc);
    const int tid = threadIdx.x;
    const int wid = tid >> 5;
    const int lane = tid & 31;
    const int wm = wid & 1;
    const int wn = wid >> 1;
    const int row0 = blockIdx.x * 128;
    const int col0 = blockIdx.y * 128;

    const int c0r = (tid) >> 2,        c0v = (tid) & 3;
    const int c1r = (tid + 256) >> 2,  c1v = (tid + 256) & 3;
    const u32 s0 = (u32)(c0r * GSTRIDE + c0v * 16);
    const u32 s1 = (u32)(c1r * GSTRIDE + c1v * 16);
    const size_t ga0 = (size_t)(row0 + c0r) * DIM + c0v * 8;
    const size_t ga1 = (size_t)(row0 + c1r) * DIM + c1v * 8;
    const size_t gb0 = (size_t)(col0 + c0r) * DIM + c0v * 8;
    const size_t gb1 = (size_t)(col0 + c1r) * DIM + c1v * 8;

    const u32 aRowOff = (u32)((wm * 64 + (lane & 7) + ((lane >> 3) & 1) * 8) * GSTRIDE
                              + (lane >> 4) * 16);
    const u32 bRowOff = (u32)((wn * 32 + (lane & 7) + (lane >> 4) * 8) * GSTRIDE
                              + ((lane >> 3) & 1) * 16);

    float acc[4][4][4];
    #pragma unroll
    for (int i = 0; i < 4; i++)
        #pragma unroll
        for (int j = 0; j < 4; j++)
            #pragma unroll
            for (int q = 0; q < 4; q++) acc[i][j][q] = 0.f;

    {
        u32 st = sb;
        CP_ASYNC16(st + OFF_AHI + s0, g_Ahi + ga0);
        CP_ASYNC16(st + OFF_AHI + s1, g_Ahi + ga1);
        CP_ASYNC16(st + OFF_ALO + s0, g_Alo + ga0);
        CP_ASYNC16(st + OFF_ALO + s1, g_Alo + ga1);
        CP_ASYNC16(st + OFF_BHI + s0, g_WhiT + gb0);
        CP_ASYNC16(st + OFF_BHI + s1, g_WhiT + gb1);
        CP_ASYNC16(st + OFF_BLO + s0, g_WloT + gb0);
        CP_ASYNC16(st + OFF_BLO + s1, g_WloT + gb1);
        CP_COMMIT();
    }

    for (int kt = 0; kt < NKT; kt++) {
        if (kt + 1 < NKT) {
            const int kc = (kt + 1) * 32;
            u32 st = sb + ((kt + 1) & 1) * STAGE_BYTES;
            CP_ASYNC16(st + OFF_AHI + s0, g_Ahi + ga0 + kc);
            CP_ASYNC16(st + OFF_AHI + s1, g_Ahi + ga1 + kc);
            CP_ASYNC16(st + OFF_ALO + s0, g_Alo + ga0 + kc);
            CP_ASYNC16(st + OFF_ALO + s1, g_Alo + ga1 + kc);
            CP_ASYNC16(st + OFF_BHI + s0, g_WhiT + gb0 + kc);
            CP_ASYNC16(st + OFF_BHI + s1, g_WhiT + gb1 + kc);
            CP_ASYNC16(st + OFF_BLO + s0, g_WloT + gb0 + kc);
            CP_ASYNC16(st + OFF_BLO + s1, g_WloT + gb1 + kc);
            CP_COMMIT();
            CP_WAIT(1);
        } else {
            CP_WAIT(0);
        }
        __syncthreads();

        const u32 st = sb + (kt & 1) * STAGE_BYTES;
        const u32 aHi = st + OFF_AHI + aRowOff;
        const u32 aLo = st + OFF_ALO + aRowOff;
        const u32 bHi = st + OFF_BHI + bRowOff;
        const u32 bLo = st + OFF_BLO + bRowOff;

        #pragma unroll
        for (int ks = 0; ks < 2; ks++) {
            u32 ah[4][4], al[4][4], bh[2][4], bl[2][4];
            #pragma unroll
            for (int mt = 0; mt < 4; mt++) {
                ldsm4(ah[mt], aHi + mt * (16 * GSTRIDE) + ks * 32);
                ldsm4(al[mt], aLo + mt * (16 * GSTRIDE) + ks * 32);
            }
            #pragma unroll
            for (int g = 0; g < 2; g++) {
                ldsm4(bh[g], bHi + g * (16 * GSTRIDE) + ks * 32);
                ldsm4(bl[g], bLo + g * (16 * GSTRIDE) + ks * 32);
            }
            #pragma unroll
            for (int mt = 0; mt < 4; mt++)
                #pragma unroll
                for (int nt = 0; nt < 4; nt++) {
                    float* c = acc[mt][nt];
                    const u32* bhp = &bh[nt >> 1][(nt & 1) * 2];
                    const u32* blp = &bl[nt >> 1][(nt & 1) * 2];
                    mma16816(c, ah[mt], bhp);
                    mma16816(c, ah[mt], blp);
                    mma16816(c, al[mt], bhp);
                }
        }
        __syncthreads();
    }

    #pragma unroll
    for (int nt = 0; nt < 4; nt++) {
        const int n = col0 + wn * 32 + nt * 8 + (lane & 3) * 2;
        if (n >= NVOC) continue;
        const float b0 = __ldg(bias + n);
        const float b1 = __ldg(bias + n + 1);
        #pragma unroll
        for (int mt = 0; mt < 4; mt++) {
            const int m = row0 + wm * 64 + mt * 16 + (lane >> 2);
            float* cp0 = C + (size_t)m * NVOC + n;
            float* cp1 = C + (size_t)(m + 8) * NVOC + n;
            *(float2*)cp0 = make_float2(acc[mt][nt][0] + b0, acc[mt][nt][1] + b1);
            *(float2*)cp1 = make_float2(acc[mt][nt][2] + b0, acc[mt][nt][3] + b1);
        }
    }
}

// =====================================================================
extern "C" void kernel_launch(void* const* d_in, const int* in_sizes, int n_in,
                              void* d_out, int out_size)
{
    const int*   tokens = (const int*)  d_in[0];
    const float* emb    = (const float*)d_in[1];
    const float* Wh     = (const float*)d_in[2];
    const float* Uh     = (const float*)d_in[3];
    const float* b      = (const float*)d_in[4];
    const float* fc_w   = (const float*)d_in[5];
    const float* fc_b   = (const float*)d_in[6];
    float* C = (float*)d_out;
    (void)in_sizes; (void)n_in; (void)out_size;

    cudaFuncSetAttribute(rnn_kernel,
                         cudaFuncAttributeMaxDynamicSharedMemorySize, RNN_SMEM);
    cudaFuncSetAttribute(gemm_hmma_kernel,
                         cudaFuncAttributeMaxDynamicSharedMemorySize, GEMM_SMEM);

    dim3 wgrid(NVOC / 32, DIM / 32);
    convW_kernel<<<wgrid, 256>>>(fc_w);

    rnn_kernel<<<NCTA, RNN_THREADS, RNN_SMEM>>>(tokens, emb, Wh, Uh, b);

    dim3 ggrid((BATCH * SEQ) / 128, NVOC_PAD / 128);
    gemm_hmma_kernel<<<ggrid, 256, GEMM_SMEM>>>(fc_b, C);
}